// round 13
// baseline (speedup 1.0000x reference)
#include <cuda_runtime.h>
#include <cuda_fp16.h>
#include <math.h>
#include <stdint.h>

#define G_     8
#define KS_    7
#define NTAP_  49
#define HID_   32
#define OMEGA_ 10.0f

// ---------------------------------------------------------------------------
// Device globals (static — no allocation)
// ---------------------------------------------------------------------------
// A in MMA-fragment layout: [chunk=mt*49*4.. ][wm(2)][ms*4+ks(16)][lane(32)][4 b32]
__device__ __align__(256) __half d_Af[2 * NTAP_ * 4 * 128 * 64];   // 3.2MB
__device__ __align__(256) __half d_xT[16 * 4096 * 256];            // 16.8MB
__device__ int d_mask[G_ * NTAP_];
__device__ int d_utap[NTAP_];
__device__ int d_nu;

// ---------------------------------------------------------------------------
// PTX helpers (baseline sm_80-class only: compiles for .target sm_103)
// ---------------------------------------------------------------------------
__device__ __forceinline__ uint32_t smem_u32(const void* p) {
    uint32_t a;
    asm("{ .reg .u64 t; cvta.to.shared.u64 t, %1; cvt.u32.u64 %0, t; }" : "=r"(a) : "l"(p));
    return a;
}
__device__ __forceinline__ void cp16(uint32_t dst, const void* src, uint32_t sz) {
    asm volatile("cp.async.cg.shared.global [%0], [%1], 16, %2;"
                 :: "r"(dst), "l"(src), "r"(sz) : "memory");
}
#define CP_COMMIT() asm volatile("cp.async.commit_group;" ::: "memory")
#define CP_WAIT1()  asm volatile("cp.async.wait_group 1;" ::: "memory")

__device__ __forceinline__ void ldsm4(uint32_t* r, uint32_t a) {
    asm volatile("ldmatrix.sync.aligned.m8n8.x4.shared.b16 {%0,%1,%2,%3}, [%4];"
                 : "=r"(r[0]), "=r"(r[1]), "=r"(r[2]), "=r"(r[3]) : "r"(a));
}
__device__ __forceinline__ void mma16816(float* d, const uint32_t* a, const uint32_t* b) {
    asm volatile(
        "mma.sync.aligned.m16n8k16.row.col.f32.f16.f16.f32 "
        "{%0,%1,%2,%3}, {%4,%5,%6,%7}, {%8,%9}, {%0,%1,%2,%3};"
        : "+f"(d[0]), "+f"(d[1]), "+f"(d[2]), "+f"(d[3])
        : "r"(a[0]), "r"(a[1]), "r"(a[2]), "r"(a[3]), "r"(b[0]), "r"(b[1]));
}

// Replicate jnp.linspace(-1,1,7) fp32 exactly
__device__ __forceinline__ float grid_val(int i) {
    if (i == 6) return 1.0f;
    const float step = 2.0f / 6.0f;
    return __fadd_rn(__fmul_rn((float)i, step), -1.0f);
}

// ---------------------------------------------------------------------------
// Mask: per-gout disk masks + union tap list. Mirrors JAX fp32 op sequence.
// ---------------------------------------------------------------------------
__global__ void mask_kernel(const float* __restrict__ ge) {
    __shared__ int um[NTAP_];
    int t = threadIdx.x;
    if (t < NTAP_) {
        float y = grid_val(t / KS_);
        float x = grid_val(t % KS_);
        int u = 0;
        for (int g = 0; g < G_; g++) {
            float th = ge[g];
            float ct = cosf(-th), st = sinf(-th);
            float ny = __fadd_rn(__fmul_rn(ct, y), -__fmul_rn(st, x));
            float nx = __fadd_rn(__fmul_rn(st, y),  __fmul_rn(ct, x));
            float ss = __fadd_rn(__fmul_rn(ny, ny), __fmul_rn(nx, nx));
            int mk = (sqrtf(ss) <= 1.0f) ? 1 : 0;
            d_mask[g * NTAP_ + t] = mk;
            u |= mk;
        }
        um[t] = u;
    }
    __syncthreads();
    if (t == 0) {
        int n = 0;
        for (int i = 0; i < NTAP_; i++)
            if (um[i]) d_utap[n++] = i;
        d_nu = n;
    }
}

// ---------------------------------------------------------------------------
// Transpose + fp16 convert: x[b][c][pix] -> xT[b][pix][c]
// ---------------------------------------------------------------------------
__global__ void xt_kernel(const float* __restrict__ x) {
    __shared__ float s[64][129];
    int p0 = blockIdx.x * 64;
    int b  = blockIdx.y;
    int c0 = blockIdx.z * 128;
    int tid = threadIdx.x;
    int c_off = tid >> 6;
    int px = tid & 63;
    const float* xb = x + (size_t)b * 256 * 4096 + p0 + px;
#pragma unroll 4
    for (int cb = 0; cb < 32; cb++) {
        int cl = cb * 4 + c_off;
        s[px][cl] = xb[(size_t)(c0 + cl) * 4096];
    }
    __syncthreads();
#pragma unroll
    for (int r = 0; r < 4; r++) {
        int idx = tid + r * 256;       // 0..1023
        int p = idx >> 4;              // 0..63
        int u = idx & 15;              // 16 uint4 per 128-ch half
        __half hb[8];
#pragma unroll
        for (int e = 0; e < 8; e++)
            hb[e] = __float2half_rn(s[p][u * 8 + e]);
        size_t dst = ((size_t)b * 4096 + p0 + p) * 256 + c0 + u * 8;
        *(uint4*)(d_xT + dst) = *(uint4*)hb;
    }
}

// ---------------------------------------------------------------------------
// SIREN kernel-net -> masked fp16 A in MMA fragment layout:
// half index = chunk*8192 + wm*4096 + (ms*4+ksq)*256 + lane*8 + reg*2 + half
// chunk = (mt*49+tap)*4+cc
// ---------------------------------------------------------------------------
__global__ void siren_kernel(const float* __restrict__ ge,
                             const float* __restrict__ W1, const float* __restrict__ b1,
                             const float* __restrict__ W2, const float* __restrict__ b2,
                             const float* __restrict__ W3, const float* __restrict__ b3) {
    __shared__ float pts[NTAP_ * 3];
    __shared__ float h1[NTAP_ * HID_];
    __shared__ float h2[NTAP_ * HID_];
    __shared__ int   s_mask[NTAP_];

    int gout = blockIdx.x >> 3;
    int gin  = blockIdx.x & 7;
    int tid  = threadIdx.x;

    if (tid < NTAP_) {
        s_mask[tid] = d_mask[gout * NTAP_ + tid];
        float tho = ge[gout];
        float thi = ge[gin];
        float ct = cosf(-tho);
        float st = sinf(-tho);
        const float twopi = 6.28318530717958647692f;
        const float pif   = 3.14159265358979323846f;
        float d = __fadd_rn(thi, -tho);
        float m = fmodf(d, twopi);
        if (m < 0.0f) m = __fadd_rn(m, twopi);
        float ag = __fadd_rn(__fdiv_rn(m, pif), -1.0f);
        float y = grid_val(tid / KS_);
        float x = grid_val(tid % KS_);
        pts[tid * 3 + 0] = __fadd_rn(__fmul_rn(ct, y), -__fmul_rn(st, x));
        pts[tid * 3 + 1] = __fadd_rn(__fmul_rn(st, y),  __fmul_rn(ct, x));
        pts[tid * 3 + 2] = ag;
    }
    __syncthreads();

    for (int i = tid; i < NTAP_ * HID_; i += 256) {
        int t = i >> 5, h = i & 31;
        float v = b1[h];
        v = fmaf(pts[t * 3 + 0], W1[0 * HID_ + h], v);
        v = fmaf(pts[t * 3 + 1], W1[1 * HID_ + h], v);
        v = fmaf(pts[t * 3 + 2], W1[2 * HID_ + h], v);
        h1[i] = sinf(OMEGA_ * v);
    }
    __syncthreads();

    for (int i = tid; i < NTAP_ * HID_; i += 256) {
        int t = i >> 5, h = i & 31;
        float v = b2[h];
#pragma unroll
        for (int k = 0; k < HID_; k++)
            v = fmaf(h1[t * HID_ + k], W2[k * HID_ + h], v);
        h2[i] = sinf(OMEGA_ * v);
    }
    __syncthreads();

    for (int i = tid; i < NTAP_ * 1024; i += 256) {
        int t = i >> 10, o = i & 1023;
        float v = b3[o];
#pragma unroll
        for (int k = 0; k < HID_; k++)
            v = fmaf(h2[t * HID_ + k], W3[k * 1024 + o], v);
        if (!s_mask[t]) v = 0.0f;
        int cout = o >> 5, cin = o & 31;
        int c = cin * G_ + gin;           // 0..255
        int mt = gout >> 2;
        int m  = ((gout & 3) << 5) + cout;  // 0..127
        int cc = c >> 6, k = c & 63;
        // fragment coords for mma.m16n8k16 A operand
        int wm  = m >> 6;
        int ms  = (m >> 4) & 3;
        int mr  = m & 15;
        int ksq = k >> 4;
        int kr  = k & 15;
        int reg  = (mr >= 8 ? 1 : 0) + (kr >= 8 ? 2 : 0);
        int lane = (mr & 7) * 4 + ((kr & 7) >> 1);
        int half = kr & 1;
        size_t idx = ((size_t)((mt * NTAP_ + t) * 4 + cc)) * 8192
                   + (size_t)wm * 4096 + (ms * 4 + ksq) * 256
                   + lane * 8 + reg * 2 + half;
        d_Af[idx] = __float2half_rn(v);
    }
}

// ---------------------------------------------------------------------------
// HMMA conv: 256 threads / 8 warps, 2 CTAs/SM, block tile M=128 x N=128px,
// warp 64x32, K-chunk=64, single-term fp16. B via 3-stage cp.async smem;
// A loaded DIRECTLY from L2 in fragment layout (LDG.128), prefetched 1 ks
// ahead. Crossbar per chunk = B only.
// ---------------------------------------------------------------------------
#define STAGE_SZ 16384
#define SM_BIAS  (3 * STAGE_SZ)
#define SM_UTAP  (SM_BIAS + 128)
#define SM_NU    (SM_UTAP + 4 * NTAP_)
#define SMEM_DYN (SM_NU + 16)

struct ConvCtx {
    uint32_t sbase;
    int tid, mt, b, h0;
    const int* utap;
};

__device__ __forceinline__ void stage_chunk(const ConvCtx& c, int i, int s) {
    int tap = c.utap[i >> 2];
    int cc  = i & 3;
    uint32_t stg = c.sbase + (uint32_t)s * STAGE_SZ;

    // B: 128 pixel rows x 64k (128B); 2 threads per pixel, 4 uint4 each
    int dy = tap / KS_ - 3, dx = tap % KS_ - 3;
    int pix  = c.tid >> 1;
    int half = c.tid & 1;
    int hh = c.h0 + (pix >> 6) + dy;
    int ww = (pix & 63) + dx;
    bool ok = (hh >= 0) && (hh < 64) && (ww >= 0) && (ww < 64);
    size_t gpix = ok ? ((size_t)c.b * 4096 + (size_t)hh * 64 + ww) : 0;
    const char* gb = (const char*)(d_xT + gpix * 256 + cc * 64);
    uint32_t sz = ok ? 16u : 0u;
    uint32_t rowbase = (uint32_t)(pix * 128);
    uint32_t sw = (uint32_t)((pix & 7) << 4);
#pragma unroll
    for (int u = 0; u < 4; u++) {
        int uu = half * 4 + u;
        uint32_t d = rowbase + ((uu * 16) ^ sw);
        cp16(stg + d, gb + uu * 16, sz);
    }
}

__global__ void __launch_bounds__(256, 2)
conv_kernel(const float* __restrict__ bias, float* __restrict__ out) {
    extern __shared__ char sm[];
    uint32_t sbase = smem_u32(sm);
    int tid  = threadIdx.x;
    int lane = tid & 31;
    int wid  = tid >> 5;
    int wm   = wid & 1;     // M half (64 rows)
    int wn   = wid >> 1;    // N 32-px block (0..3)

    if (tid < 32) ((float*)(sm + SM_BIAS))[tid] = bias[tid];
    if (tid >= 64 && tid < 64 + NTAP_) ((int*)(sm + SM_UTAP))[tid - 64] = d_utap[tid - 64];
    if (tid == 32) *((int*)(sm + SM_NU)) = d_nu;
    __syncthreads();

    ConvCtx c;
    c.sbase = sbase;
    c.tid = tid;
    c.utap = (const int*)(sm + SM_UTAP);
    int nu = *((const int*)(sm + SM_NU));
    int nc = nu << 2;

    // 1024 tiles: [hp:32][b:16][mt:2], N covers image rows h0,h0+1
    int T  = blockIdx.x;
    c.mt   = T & 1;
    c.b    = (T >> 1) & 15;
    c.h0   = (T >> 5) << 1;

    // B LDSM geometry (constant):
    int brow = wn * 32 + (lane & 7) + ((lane & 16) >> 1);   // + ns*16
    uint32_t b_rowoff = (uint32_t)(brow * 128);
    uint32_t b_kb0    = (uint32_t)((lane & 8) << 1);
    uint32_t b_swz    = (uint32_t)((brow & 7) << 4);

    // A fragment base (uint4 units): chunk*1024 + wm*512 + lane
    const uint4* gAf = (const uint4*)d_Af;
    uint32_t a_tbase = (uint32_t)(wm * 512 + lane);

    float acc[4][4][4];
#pragma unroll
    for (int ms = 0; ms < 4; ms++)
#pragma unroll
        for (int nf = 0; nf < 4; nf++)
#pragma unroll
            for (int q = 0; q < 4; q++) acc[ms][nf][q] = 0.0f;

    stage_chunk(c, 0, 0);
    CP_COMMIT();
    stage_chunk(c, 1, 1);
    CP_COMMIT();

    int s = 0;
    for (int i = 0; i < nc; i++) {
        CP_WAIT1();                 // stage i resident (i+1 may be in flight)
        __syncthreads();            // everyone finished compute(i-1)
        if (i + 2 < nc) {           // prefetch into buffer (i+2)%3
            int s2 = s + 2; if (s2 >= 3) s2 -= 3;
            stage_chunk(c, i + 2, s2);
            CP_COMMIT();
        }

        uint32_t stg = sbase + (uint32_t)s * STAGE_SZ;
        int tap = c.utap[i >> 2];
        int cc  = i & 3;
        const uint4* ga = gAf + (size_t)((c.mt * NTAP_ + tap) * 4 + cc) * 1024 + a_tbase;

        uint4 a[2][4];
        // preload ks=0 A fragments (LDG.128 from L2, fragment layout)
#pragma unroll
        for (int ms = 0; ms < 4; ms++)
            a[0][ms] = __ldg(ga + ms * 128);

#pragma unroll
        for (int ks = 0; ks < 4; ks++) {
            int cur = ks & 1, nxt = cur ^ 1;
            if (ks < 3) {
#pragma unroll
                for (int ms = 0; ms < 4; ms++)
                    a[nxt][ms] = __ldg(ga + ms * 128 + (ks + 1) * 32);
            }
            uint32_t bf[2][4];
            uint32_t bkb = b_kb0 + (uint32_t)(ks * 32);
#pragma unroll
            for (int ns = 0; ns < 2; ns++)
                ldsm4(bf[ns], stg + b_rowoff + (uint32_t)(ns * 2048) + (bkb ^ b_swz));
#pragma unroll
            for (int ms = 0; ms < 4; ms++)
#pragma unroll
                for (int nf = 0; nf < 4; nf++)
                    mma16816(acc[ms][nf], (const uint32_t*)&a[cur][ms],
                             &bf[nf >> 1][(nf & 1) * 2]);
        }
        if (++s >= 3) s = 0;
    }

    // epilogue: out[b][cout][gout][h][w] + bias[cout]
    const float* sb = (const float*)(sm + SM_BIAS);
    int h = c.h0 + (wn >> 1);
    int wbase = (wn & 1) * 32;
#pragma unroll
    for (int ms = 0; ms < 4; ms++) {
#pragma unroll
        for (int half = 0; half < 2; half++) {
            int rm = wm * 64 + ms * 16 + (lane >> 2) + half * 8;
            int gout = c.mt * 4 + (rm >> 5);
            int cout = rm & 31;
            float bv = sb[cout];
            float* ob = out + (((size_t)c.b * 32 + cout) * 8 + gout) * 4096 + h * 64;
#pragma unroll
            for (int nf = 0; nf < 4; nf++) {
                int w = wbase + nf * 8 + (lane & 3) * 2;
                float2 v;
                v.x = acc[ms][nf][half * 2 + 0] + bv;
                v.y = acc[ms][nf][half * 2 + 1] + bv;
                *(float2*)(ob + w) = v;
            }
        }
    }
}

// ---------------------------------------------------------------------------
extern "C" void kernel_launch(void* const* d_in, const int* in_sizes, int n_in,
                              void* d_out, int out_size) {
    const float* x    = (const float*)d_in[0];
    const float* ge   = (const float*)d_in[1];
    const float* W1   = (const float*)d_in[2];
    const float* b1   = (const float*)d_in[3];
    const float* W2   = (const float*)d_in[4];
    const float* b2   = (const float*)d_in[5];
    const float* W3   = (const float*)d_in[6];
    const float* b3   = (const float*)d_in[7];
    const float* bias = (const float*)d_in[8];
    float* out = (float*)d_out;

    cudaFuncSetAttribute(conv_kernel, cudaFuncAttributeMaxDynamicSharedMemorySize, SMEM_DYN);

    mask_kernel<<<1, 64>>>(ge);
    xt_kernel<<<dim3(64, 16, 2), 256>>>(x);
    siren_kernel<<<G_ * G_, 256>>>(ge, W1, b1, W2, b2, W3, b3);
    conv_kernel<<<1024, 256, SMEM_DYN>>>(bias, out);
}

// round 14
// speedup vs baseline: 1.7831x; 1.7831x over previous
#include <cuda_runtime.h>
#include <cuda_fp16.h>
#include <math.h>
#include <stdint.h>

#define G_     8
#define KS_    7
#define NTAP_  49
#define HID_   32
#define OMEGA_ 10.0f

// ---------------------------------------------------------------------------
// Device globals (static — no allocation)
// ---------------------------------------------------------------------------
__device__ __align__(256) __half d_A[2 * NTAP_ * 4 * 128 * 64];    // 3.2MB
__device__ __align__(256) __half d_xT[16 * 4096 * 256];            // 16.8MB
__device__ int d_mask[G_ * NTAP_];
__device__ int d_utap[NTAP_];
__device__ int d_nu;

// ---------------------------------------------------------------------------
// PTX helpers (baseline sm_80-class only: compiles for .target sm_103)
// ---------------------------------------------------------------------------
__device__ __forceinline__ uint32_t smem_u32(const void* p) {
    uint32_t a;
    asm("{ .reg .u64 t; cvta.to.shared.u64 t, %1; cvt.u32.u64 %0, t; }" : "=r"(a) : "l"(p));
    return a;
}
__device__ __forceinline__ void cp16(uint32_t dst, const void* src, uint32_t sz) {
    asm volatile("cp.async.cg.shared.global [%0], [%1], 16, %2;"
                 :: "r"(dst), "l"(src), "r"(sz) : "memory");
}
#define CP_COMMIT() asm volatile("cp.async.commit_group;" ::: "memory")
#define CP_WAIT1()  asm volatile("cp.async.wait_group 1;" ::: "memory")
#define CP_WAIT0()  asm volatile("cp.async.wait_group 0;" ::: "memory")

__device__ __forceinline__ void ldsm4(uint32_t* r, uint32_t a) {
    asm volatile("ldmatrix.sync.aligned.m8n8.x4.shared.b16 {%0,%1,%2,%3}, [%4];"
                 : "=r"(r[0]), "=r"(r[1]), "=r"(r[2]), "=r"(r[3]) : "r"(a));
}
__device__ __forceinline__ void mma16816(float* d, const uint32_t* a, const uint32_t* b) {
    asm volatile(
        "mma.sync.aligned.m16n8k16.row.col.f32.f16.f16.f32 "
        "{%0,%1,%2,%3}, {%4,%5,%6,%7}, {%8,%9}, {%0,%1,%2,%3};"
        : "+f"(d[0]), "+f"(d[1]), "+f"(d[2]), "+f"(d[3])
        : "r"(a[0]), "r"(a[1]), "r"(a[2]), "r"(a[3]), "r"(b[0]), "r"(b[1]));
}

// Replicate jnp.linspace(-1,1,7) fp32 exactly
__device__ __forceinline__ float grid_val(int i) {
    if (i == 6) return 1.0f;
    const float step = 2.0f / 6.0f;
    return __fadd_rn(__fmul_rn((float)i, step), -1.0f);
}

// ---------------------------------------------------------------------------
// Mask: per-gout disk masks + union tap list. Mirrors JAX fp32 op sequence.
// ---------------------------------------------------------------------------
__global__ void mask_kernel(const float* __restrict__ ge) {
    __shared__ int um[NTAP_];
    int t = threadIdx.x;
    if (t < NTAP_) {
        float y = grid_val(t / KS_);
        float x = grid_val(t % KS_);
        int u = 0;
        for (int g = 0; g < G_; g++) {
            float th = ge[g];
            float ct = cosf(-th), st = sinf(-th);
            float ny = __fadd_rn(__fmul_rn(ct, y), -__fmul_rn(st, x));
            float nx = __fadd_rn(__fmul_rn(st, y),  __fmul_rn(ct, x));
            float ss = __fadd_rn(__fmul_rn(ny, ny), __fmul_rn(nx, nx));
            int mk = (sqrtf(ss) <= 1.0f) ? 1 : 0;
            d_mask[g * NTAP_ + t] = mk;
            u |= mk;
        }
        um[t] = u;
    }
    __syncthreads();
    if (t == 0) {
        int n = 0;
        for (int i = 0; i < NTAP_; i++)
            if (um[i]) d_utap[n++] = i;
        d_nu = n;
    }
}

// ---------------------------------------------------------------------------
// Transpose + fp16 convert: x[b][c][pix] -> xT[b][pix][c]
// ---------------------------------------------------------------------------
__global__ void xt_kernel(const float* __restrict__ x) {
    __shared__ float s[64][129];
    int p0 = blockIdx.x * 64;
    int b  = blockIdx.y;
    int c0 = blockIdx.z * 128;
    int tid = threadIdx.x;
    int c_off = tid >> 6;
    int px = tid & 63;
    const float* xb = x + (size_t)b * 256 * 4096 + p0 + px;
#pragma unroll 4
    for (int cb = 0; cb < 32; cb++) {
        int cl = cb * 4 + c_off;
        s[px][cl] = xb[(size_t)(c0 + cl) * 4096];
    }
    __syncthreads();
#pragma unroll
    for (int r = 0; r < 4; r++) {
        int idx = tid + r * 256;       // 0..1023
        int p = idx >> 4;              // 0..63
        int u = idx & 15;              // 16 uint4 per 128-ch half
        __half hb[8];
#pragma unroll
        for (int e = 0; e < 8; e++)
            hb[e] = __float2half_rn(s[p][u * 8 + e]);
        size_t dst = ((size_t)b * 4096 + p0 + p) * 256 + c0 + u * 8;
        *(uint4*)(d_xT + dst) = *(uint4*)hb;
    }
}

// ---------------------------------------------------------------------------
// SIREN kernel-net -> masked fp16 A tiles [mt][tap][cc][m=128][k=64]
// grid 256: (gout, gin, oq) — each block computes 1/4 of layer-3 outputs.
// ---------------------------------------------------------------------------
__global__ void siren_kernel(const float* __restrict__ ge,
                             const float* __restrict__ W1, const float* __restrict__ b1,
                             const float* __restrict__ W2, const float* __restrict__ b2,
                             const float* __restrict__ W3, const float* __restrict__ b3) {
    __shared__ float pts[NTAP_ * 3];
    __shared__ float h1[NTAP_ * HID_];
    __shared__ float h2[NTAP_ * HID_];
    __shared__ int   s_mask[NTAP_];

    int gout = blockIdx.x >> 5;
    int gin  = (blockIdx.x >> 2) & 7;
    int oq   = blockIdx.x & 3;
    int tid  = threadIdx.x;

    if (tid < NTAP_) {
        s_mask[tid] = d_mask[gout * NTAP_ + tid];
        float tho = ge[gout];
        float thi = ge[gin];
        float ct = cosf(-tho);
        float st = sinf(-tho);
        const float twopi = 6.28318530717958647692f;
        const float pif   = 3.14159265358979323846f;
        float d = __fadd_rn(thi, -tho);
        float m = fmodf(d, twopi);
        if (m < 0.0f) m = __fadd_rn(m, twopi);
        float ag = __fadd_rn(__fdiv_rn(m, pif), -1.0f);
        float y = grid_val(tid / KS_);
        float x = grid_val(tid % KS_);
        pts[tid * 3 + 0] = __fadd_rn(__fmul_rn(ct, y), -__fmul_rn(st, x));
        pts[tid * 3 + 1] = __fadd_rn(__fmul_rn(st, y),  __fmul_rn(ct, x));
        pts[tid * 3 + 2] = ag;
    }
    __syncthreads();

    for (int i = tid; i < NTAP_ * HID_; i += 256) {
        int t = i >> 5, h = i & 31;
        float v = b1[h];
        v = fmaf(pts[t * 3 + 0], W1[0 * HID_ + h], v);
        v = fmaf(pts[t * 3 + 1], W1[1 * HID_ + h], v);
        v = fmaf(pts[t * 3 + 2], W1[2 * HID_ + h], v);
        h1[i] = sinf(OMEGA_ * v);
    }
    __syncthreads();

    for (int i = tid; i < NTAP_ * HID_; i += 256) {
        int t = i >> 5, h = i & 31;
        float v = b2[h];
#pragma unroll
        for (int k = 0; k < HID_; k++)
            v = fmaf(h1[t * HID_ + k], W2[k * HID_ + h], v);
        h2[i] = sinf(OMEGA_ * v);
    }
    __syncthreads();

    // quarter of the 49*1024 layer-3 outputs (contiguous range)
    for (int ii = tid; ii < NTAP_ * 256; ii += 256) {
        int i = oq * (NTAP_ * 256) + ii;
        int t = i >> 10, o = i & 1023;
        float v = b3[o];
#pragma unroll
        for (int k = 0; k < HID_; k++)
            v = fmaf(h2[t * HID_ + k], W3[k * 1024 + o], v);
        if (!s_mask[t]) v = 0.0f;
        int cout = o >> 5, cin = o & 31;
        int c = cin * G_ + gin;
        int mt = gout >> 2, m = ((gout & 3) << 5) + cout;
        size_t addr = ((size_t)((mt * NTAP_ + t) * 4 + (c >> 6))) * 8192 + m * 64 + (c & 63);
        d_A[addr] = __float2half_rn(v);
    }
}

// ---------------------------------------------------------------------------
// HMMA conv: PERSISTENT, 296 CTAs (2/SM), 256 threads / 8 warps, block tile
// M=128 x N=128px, warp 64x32, K-chunk=64, single-term fp16, 3-stage
// cp.async pipeline (1 sync/chunk). Each CTA loops over tiles to remove the
// partial-wave tail.
// ---------------------------------------------------------------------------
#define ST_A     0
#define ST_B     16384
#define STAGE_SZ 32768
#define SM_BIAS  (3 * STAGE_SZ)
#define SM_UTAP  (SM_BIAS + 128)
#define SM_NU    (SM_UTAP + 4 * NTAP_)
#define SMEM_DYN (SM_NU + 16)
#define NCTA     296

struct ConvCtx {
    uint32_t sbase;
    int tid, mt, b, h0;
    const int* utap;
};

__device__ __forceinline__ void stage_chunk(const ConvCtx& c, int i, int s) {
    int tap = c.utap[i >> 2];
    int cc  = i & 3;
    uint32_t stg = c.sbase + (uint32_t)s * STAGE_SZ;

    // A: [128m x 64k] rows of 128B, 16B-XOR swizzle (4 uint4/thread)
    const char* ga = (const char*)(d_A + (size_t)((c.mt * NTAP_ + tap) * 4 + cc) * 8192);
#pragma unroll
    for (int r = 0; r < 4; r++) {
        int idx = c.tid + (r << 8);
        int m = idx >> 3, u = idx & 7;
        uint32_t d = (uint32_t)(m * 128 + ((u * 16) ^ ((m & 7) << 4)));
        cp16(stg + ST_A + d, ga + idx * 16, 16);
    }
    // B: 128 pixel rows x 64k (128B); 2 threads per pixel, 4 uint4 each
    int dy = tap / KS_ - 3, dx = tap % KS_ - 3;
    int pix  = c.tid >> 1;
    int half = c.tid & 1;
    int hh = c.h0 + (pix >> 6) + dy;
    int ww = (pix & 63) + dx;
    bool ok = (hh >= 0) && (hh < 64) && (ww >= 0) && (ww < 64);
    size_t gpix = ok ? ((size_t)c.b * 4096 + (size_t)hh * 64 + ww) : 0;
    const char* gb = (const char*)(d_xT + gpix * 256 + cc * 64);
    uint32_t sz = ok ? 16u : 0u;
    uint32_t rowbase = (uint32_t)(pix * 128);
    uint32_t sw = (uint32_t)((pix & 7) << 4);
#pragma unroll
    for (int u = 0; u < 4; u++) {
        int uu = half * 4 + u;
        uint32_t d = rowbase + ((uu * 16) ^ sw);
        cp16(stg + ST_B + d, gb + uu * 16, sz);
    }
}

__global__ void __launch_bounds__(256, 2)
conv_kernel(const float* __restrict__ bias, float* __restrict__ out) {
    extern __shared__ char sm[];
    uint32_t sbase = smem_u32(sm);
    int tid  = threadIdx.x;
    int lane = tid & 31;
    int wid  = tid >> 5;
    int wm   = wid & 1;     // M half (64 rows)
    int wn   = wid >> 1;    // N 32-px block (0..3)

    if (tid < 32) ((float*)(sm + SM_BIAS))[tid] = bias[tid];
    if (tid >= 64 && tid < 64 + NTAP_) ((int*)(sm + SM_UTAP))[tid - 64] = d_utap[tid - 64];
    if (tid == 32) *((int*)(sm + SM_NU)) = d_nu;
    __syncthreads();

    ConvCtx c;
    c.sbase = sbase;
    c.tid = tid;
    c.utap = (const int*)(sm + SM_UTAP);
    int nu = *((const int*)(sm + SM_NU));
    int nc = nu << 2;

    // B LDSM geometry (constant):
    int brow = wn * 32 + (lane & 7) + ((lane & 16) >> 1);   // + ns*16
    uint32_t b_rowoff = (uint32_t)(brow * 128);
    uint32_t b_kb0    = (uint32_t)((lane & 8) << 1);
    uint32_t b_swz    = (uint32_t)((brow & 7) << 4);
    // A LDSM geometry (constant):
    int arow = wm * 64 + (lane & 15);                       // + ms*16
    uint32_t a_rowoff = (uint32_t)(arow * 128);
    uint32_t a_kb0    = (uint32_t)((lane >> 4) << 4);
    uint32_t a_swz    = (uint32_t)((arow & 7) << 4);

    const float* sb = (const float*)(sm + SM_BIAS);

    // persistent loop over 1024 tiles: [hp:32][b:16][mt:2]
    for (int T = blockIdx.x; T < 1024; T += NCTA) {
        c.mt = T & 1;
        c.b  = (T >> 1) & 15;
        c.h0 = (T >> 5) << 1;

        float acc[4][4][4];
#pragma unroll
        for (int ms = 0; ms < 4; ms++)
#pragma unroll
            for (int nf = 0; nf < 4; nf++)
#pragma unroll
                for (int q = 0; q < 4; q++) acc[ms][nf][q] = 0.0f;

        stage_chunk(c, 0, 0);
        CP_COMMIT();
        stage_chunk(c, 1, 1);
        CP_COMMIT();

        int s = 0;
        for (int i = 0; i < nc; i++) {
            if (i + 1 < nc) { CP_WAIT1(); } else { CP_WAIT0(); }
            __syncthreads();            // everyone finished compute(i-1)
            if (i + 2 < nc) {           // prefetch into buffer (i+2)%3
                int s2 = s + 2; if (s2 >= 3) s2 -= 3;
                stage_chunk(c, i + 2, s2);
                CP_COMMIT();
            }

            uint32_t stg = sbase + (uint32_t)s * STAGE_SZ;
#pragma unroll
            for (int ks = 0; ks < 4; ks++) {
                uint32_t af[4][4], bf[2][4];
                uint32_t akb = a_kb0 + (uint32_t)(ks * 32);
                uint32_t bkb = b_kb0 + (uint32_t)(ks * 32);
#pragma unroll
                for (int ms = 0; ms < 4; ms++)
                    ldsm4(af[ms], stg + ST_A + a_rowoff + (uint32_t)(ms * 2048) + (akb ^ a_swz));
#pragma unroll
                for (int ns = 0; ns < 2; ns++)
                    ldsm4(bf[ns], stg + ST_B + b_rowoff + (uint32_t)(ns * 2048) + (bkb ^ b_swz));
#pragma unroll
                for (int ms = 0; ms < 4; ms++)
#pragma unroll
                    for (int nf = 0; nf < 4; nf++)
                        mma16816(acc[ms][nf], af[ms], &bf[nf >> 1][(nf & 1) * 2]);
            }
            if (++s >= 3) s = 0;
        }

        // epilogue: out[b][cout][gout][h][w] + bias[cout]
        int h = c.h0 + (wn >> 1);
        int wbase = (wn & 1) * 32;
#pragma unroll
        for (int ms = 0; ms < 4; ms++) {
#pragma unroll
            for (int half = 0; half < 2; half++) {
                int rm = wm * 64 + ms * 16 + (lane >> 2) + half * 8;
                int gout = c.mt * 4 + (rm >> 5);
                int cout = rm & 31;
                float bv = sb[cout];
                float* ob = out + (((size_t)c.b * 32 + cout) * 8 + gout) * 4096 + h * 64;
#pragma unroll
                for (int nf = 0; nf < 4; nf++) {
                    int w = wbase + nf * 8 + (lane & 3) * 2;
                    float2 v;
                    v.x = acc[ms][nf][half * 2 + 0] + bv;
                    v.y = acc[ms][nf][half * 2 + 1] + bv;
                    *(float2*)(ob + w) = v;
                }
            }
        }
        __syncthreads();   // don't let next tile's staging clobber buffers in use
    }
}

// ---------------------------------------------------------------------------
extern "C" void kernel_launch(void* const* d_in, const int* in_sizes, int n_in,
                              void* d_out, int out_size) {
    const float* x    = (const float*)d_in[0];
    const float* ge   = (const float*)d_in[1];
    const float* W1   = (const float*)d_in[2];
    const float* b1   = (const float*)d_in[3];
    const float* W2   = (const float*)d_in[4];
    const float* b2   = (const float*)d_in[5];
    const float* W3   = (const float*)d_in[6];
    const float* b3   = (const float*)d_in[7];
    const float* bias = (const float*)d_in[8];
    float* out = (float*)d_out;

    cudaFuncSetAttribute(conv_kernel, cudaFuncAttributeMaxDynamicSharedMemorySize, SMEM_DYN);

    mask_kernel<<<1, 64>>>(ge);
    xt_kernel<<<dim3(64, 16, 2), 256>>>(x);
    siren_kernel<<<256, 256>>>(ge, W1, b1, W2, b2, W3, b3);
    conv_kernel<<<NCTA, 256, SMEM_DYN>>>(bias, out);
}

// round 15
// speedup vs baseline: 1.7903x; 1.0040x over previous
#include <cuda_runtime.h>
#include <cuda_fp16.h>
#include <math.h>
#include <stdint.h>

#define G_     8
#define KS_    7
#define NTAP_  49
#define HID_   32
#define OMEGA_ 10.0f

// ---------------------------------------------------------------------------
// Device globals (static — no allocation)
// ---------------------------------------------------------------------------
__device__ __align__(256) __half d_A[2 * NTAP_ * 4 * 128 * 64];    // 3.2MB
__device__ __align__(256) __half d_xT[16 * 4096 * 256];            // 16.8MB
__device__ int d_mask[G_ * NTAP_];
__device__ int d_utap[NTAP_];
__device__ int d_nu;

// ---------------------------------------------------------------------------
// PTX helpers (baseline sm_80-class only: compiles for .target sm_103)
// ---------------------------------------------------------------------------
__device__ __forceinline__ uint32_t smem_u32(const void* p) {
    uint32_t a;
    asm("{ .reg .u64 t; cvta.to.shared.u64 t, %1; cvt.u32.u64 %0, t; }" : "=r"(a) : "l"(p));
    return a;
}
__device__ __forceinline__ void cp16(uint32_t dst, const void* src, uint32_t sz) {
    asm volatile("cp.async.cg.shared.global [%0], [%1], 16, %2;"
                 :: "r"(dst), "l"(src), "r"(sz) : "memory");
}
#define CP_COMMIT() asm volatile("cp.async.commit_group;" ::: "memory")
#define CP_WAIT1()  asm volatile("cp.async.wait_group 1;" ::: "memory")
#define CP_WAIT0()  asm volatile("cp.async.wait_group 0;" ::: "memory")

__device__ __forceinline__ void ldsm4(uint32_t* r, uint32_t a) {
    asm volatile("ldmatrix.sync.aligned.m8n8.x4.shared.b16 {%0,%1,%2,%3}, [%4];"
                 : "=r"(r[0]), "=r"(r[1]), "=r"(r[2]), "=r"(r[3]) : "r"(a));
}
__device__ __forceinline__ void mma16816(float* d, const uint32_t* a, const uint32_t* b) {
    asm volatile(
        "mma.sync.aligned.m16n8k16.row.col.f32.f16.f16.f32 "
        "{%0,%1,%2,%3}, {%4,%5,%6,%7}, {%8,%9}, {%0,%1,%2,%3};"
        : "+f"(d[0]), "+f"(d[1]), "+f"(d[2]), "+f"(d[3])
        : "r"(a[0]), "r"(a[1]), "r"(a[2]), "r"(a[3]), "r"(b[0]), "r"(b[1]));
}

// Replicate jnp.linspace(-1,1,7) fp32 exactly
__device__ __forceinline__ float grid_val(int i) {
    if (i == 6) return 1.0f;
    const float step = 2.0f / 6.0f;
    return __fadd_rn(__fmul_rn((float)i, step), -1.0f);
}

// ---------------------------------------------------------------------------
// Mask: per-gout disk masks + union tap list. Mirrors JAX fp32 op sequence.
// ---------------------------------------------------------------------------
__global__ void mask_kernel(const float* __restrict__ ge) {
    __shared__ int um[NTAP_];
    int t = threadIdx.x;
    if (t < NTAP_) {
        float y = grid_val(t / KS_);
        float x = grid_val(t % KS_);
        int u = 0;
        for (int g = 0; g < G_; g++) {
            float th = ge[g];
            float ct = cosf(-th), st = sinf(-th);
            float ny = __fadd_rn(__fmul_rn(ct, y), -__fmul_rn(st, x));
            float nx = __fadd_rn(__fmul_rn(st, y),  __fmul_rn(ct, x));
            float ss = __fadd_rn(__fmul_rn(ny, ny), __fmul_rn(nx, nx));
            int mk = (sqrtf(ss) <= 1.0f) ? 1 : 0;
            d_mask[g * NTAP_ + t] = mk;
            u |= mk;
        }
        um[t] = u;
    }
    __syncthreads();
    if (t == 0) {
        int n = 0;
        for (int i = 0; i < NTAP_; i++)
            if (um[i]) d_utap[n++] = i;
        d_nu = n;
    }
}

// ---------------------------------------------------------------------------
// Transpose + fp16 convert: x[b][c][pix] -> xT[b][pix][c]
// ---------------------------------------------------------------------------
__global__ void xt_kernel(const float* __restrict__ x) {
    __shared__ float s[64][129];
    int p0 = blockIdx.x * 64;
    int b  = blockIdx.y;
    int c0 = blockIdx.z * 128;
    int tid = threadIdx.x;
    int c_off = tid >> 6;
    int px = tid & 63;
    const float* xb = x + (size_t)b * 256 * 4096 + p0 + px;
#pragma unroll 4
    for (int cb = 0; cb < 32; cb++) {
        int cl = cb * 4 + c_off;
        s[px][cl] = xb[(size_t)(c0 + cl) * 4096];
    }
    __syncthreads();
#pragma unroll
    for (int r = 0; r < 4; r++) {
        int idx = tid + r * 256;       // 0..1023
        int p = idx >> 4;              // 0..63
        int u = idx & 15;              // 16 uint4 per 128-ch half
        __half hb[8];
#pragma unroll
        for (int e = 0; e < 8; e++)
            hb[e] = __float2half_rn(s[p][u * 8 + e]);
        size_t dst = ((size_t)b * 4096 + p0 + p) * 256 + c0 + u * 8;
        *(uint4*)(d_xT + dst) = *(uint4*)hb;
    }
}

// ---------------------------------------------------------------------------
// SIREN kernel-net -> masked fp16 A tiles [mt][tap][cc][m=128][k=64]
// grid 256: (gout, gin, oq) — each block computes 1/4 of layer-3 outputs.
// ---------------------------------------------------------------------------
__global__ void siren_kernel(const float* __restrict__ ge,
                             const float* __restrict__ W1, const float* __restrict__ b1,
                             const float* __restrict__ W2, const float* __restrict__ b2,
                             const float* __restrict__ W3, const float* __restrict__ b3) {
    __shared__ float pts[NTAP_ * 3];
    __shared__ float h1[NTAP_ * HID_];
    __shared__ float h2[NTAP_ * HID_];
    __shared__ int   s_mask[NTAP_];

    int gout = blockIdx.x >> 5;
    int gin  = (blockIdx.x >> 2) & 7;
    int oq   = blockIdx.x & 3;
    int tid  = threadIdx.x;

    if (tid < NTAP_) {
        s_mask[tid] = d_mask[gout * NTAP_ + tid];
        float tho = ge[gout];
        float thi = ge[gin];
        float ct = cosf(-tho);
        float st = sinf(-tho);
        const float twopi = 6.28318530717958647692f;
        const float pif   = 3.14159265358979323846f;
        float d = __fadd_rn(thi, -tho);
        float m = fmodf(d, twopi);
        if (m < 0.0f) m = __fadd_rn(m, twopi);
        float ag = __fadd_rn(__fdiv_rn(m, pif), -1.0f);
        float y = grid_val(tid / KS_);
        float x = grid_val(tid % KS_);
        pts[tid * 3 + 0] = __fadd_rn(__fmul_rn(ct, y), -__fmul_rn(st, x));
        pts[tid * 3 + 1] = __fadd_rn(__fmul_rn(st, y),  __fmul_rn(ct, x));
        pts[tid * 3 + 2] = ag;
    }
    __syncthreads();

    for (int i = tid; i < NTAP_ * HID_; i += 256) {
        int t = i >> 5, h = i & 31;
        float v = b1[h];
        v = fmaf(pts[t * 3 + 0], W1[0 * HID_ + h], v);
        v = fmaf(pts[t * 3 + 1], W1[1 * HID_ + h], v);
        v = fmaf(pts[t * 3 + 2], W1[2 * HID_ + h], v);
        h1[i] = sinf(OMEGA_ * v);
    }
    __syncthreads();

    for (int i = tid; i < NTAP_ * HID_; i += 256) {
        int t = i >> 5, h = i & 31;
        float v = b2[h];
#pragma unroll
        for (int k = 0; k < HID_; k++)
            v = fmaf(h1[t * HID_ + k], W2[k * HID_ + h], v);
        h2[i] = sinf(OMEGA_ * v);
    }
    __syncthreads();

    // quarter of the 49*1024 layer-3 outputs (contiguous range)
    for (int ii = tid; ii < NTAP_ * 256; ii += 256) {
        int i = oq * (NTAP_ * 256) + ii;
        int t = i >> 10, o = i & 1023;
        float v = b3[o];
#pragma unroll
        for (int k = 0; k < HID_; k++)
            v = fmaf(h2[t * HID_ + k], W3[k * 1024 + o], v);
        if (!s_mask[t]) v = 0.0f;
        int cout = o >> 5, cin = o & 31;
        int c = cin * G_ + gin;
        int mt = gout >> 2, m = ((gout & 3) << 5) + cout;
        size_t addr = ((size_t)((mt * NTAP_ + t) * 4 + (c >> 6))) * 8192 + m * 64 + (c & 63);
        d_A[addr] = __float2half_rn(v);
    }
}

// ---------------------------------------------------------------------------
// HMMA conv: PERSISTENT with a FLAT cross-tile chunk stream. 296 CTAs (2/SM),
// 256 threads / 8 warps, block tile M=128 x N=128px, warp 64x32, K-chunk=64,
// single-term fp16, 3-stage cp.async pipeline (1 sync/chunk) that NEVER
// drains: the staging cursor runs 2 chunks ahead, crossing tile boundaries.
// ---------------------------------------------------------------------------
#define ST_A     0
#define ST_B     16384
#define STAGE_SZ 32768
#define SM_BIAS  (3 * STAGE_SZ)
#define SM_UTAP  (SM_BIAS + 128)
#define SM_NU    (SM_UTAP + 4 * NTAP_)
#define SMEM_DYN (SM_NU + 16)
#define NCTA     296

// stage chunk i of tile T into buffer s
__device__ __forceinline__ void stage_chunk(uint32_t sbase, int tid,
                                            const int* utap, int T, int i, int s) {
    int mt = T & 1;
    int b  = (T >> 1) & 15;
    int h0 = (T >> 5) << 1;
    int tap = utap[i >> 2];
    int cc  = i & 3;
    uint32_t stg = sbase + (uint32_t)s * STAGE_SZ;

    // A: [128m x 64k] rows of 128B, 16B-XOR swizzle (4 uint4/thread)
    const char* ga = (const char*)(d_A + (size_t)((mt * NTAP_ + tap) * 4 + cc) * 8192);
#pragma unroll
    for (int r = 0; r < 4; r++) {
        int idx = tid + (r << 8);
        int m = idx >> 3, u = idx & 7;
        uint32_t d = (uint32_t)(m * 128 + ((u * 16) ^ ((m & 7) << 4)));
        cp16(stg + ST_A + d, ga + idx * 16, 16);
    }
    // B: 128 pixel rows x 64k (128B); 2 threads per pixel, 4 uint4 each
    int dy = tap / KS_ - 3, dx = tap % KS_ - 3;
    int pix  = tid >> 1;
    int half = tid & 1;
    int hh = h0 + (pix >> 6) + dy;
    int ww = (pix & 63) + dx;
    bool ok = (hh >= 0) && (hh < 64) && (ww >= 0) && (ww < 64);
    size_t gpix = ok ? ((size_t)b * 4096 + (size_t)hh * 64 + ww) : 0;
    const char* gb = (const char*)(d_xT + gpix * 256 + cc * 64);
    uint32_t sz = ok ? 16u : 0u;
    uint32_t rowbase = (uint32_t)(pix * 128);
    uint32_t sw = (uint32_t)((pix & 7) << 4);
#pragma unroll
    for (int u = 0; u < 4; u++) {
        int uu = half * 4 + u;
        uint32_t d = rowbase + ((uu * 16) ^ sw);
        cp16(stg + d + ST_B, gb + uu * 16, sz);
    }
}

__global__ void __launch_bounds__(256, 2)
conv_kernel(const float* __restrict__ bias, float* __restrict__ out) {
    extern __shared__ char sm[];
    uint32_t sbase = smem_u32(sm);
    int tid  = threadIdx.x;
    int lane = tid & 31;
    int wid  = tid >> 5;
    int wm   = wid & 1;     // M half (64 rows)
    int wn   = wid >> 1;    // N 32-px block (0..3)

    if (tid < 32) ((float*)(sm + SM_BIAS))[tid] = bias[tid];
    if (tid >= 64 && tid < 64 + NTAP_) ((int*)(sm + SM_UTAP))[tid - 64] = d_utap[tid - 64];
    if (tid == 32) *((int*)(sm + SM_NU)) = d_nu;
    __syncthreads();

    const int* utap = (const int*)(sm + SM_UTAP);
    int nu = *((const int*)(sm + SM_NU));
    int nc = nu << 2;

    // number of tiles for this CTA, total chunk count
    int ntile = 0;
    for (int T = blockIdx.x; T < 1024; T += NCTA) ntile++;
    if (ntile == 0) return;
    int total = ntile * nc;

    // B LDSM geometry (constant):
    int brow = wn * 32 + (lane & 7) + ((lane & 16) >> 1);   // + ns*16
    uint32_t b_rowoff = (uint32_t)(brow * 128);
    uint32_t b_kb0    = (uint32_t)((lane & 8) << 1);
    uint32_t b_swz    = (uint32_t)((brow & 7) << 4);
    // A LDSM geometry (constant):
    int arow = wm * 64 + (lane & 15);                       // + ms*16
    uint32_t a_rowoff = (uint32_t)(arow * 128);
    uint32_t a_kb0    = (uint32_t)((lane >> 4) << 4);
    uint32_t a_swz    = (uint32_t)((arow & 7) << 4);

    const float* sb = (const float*)(sm + SM_BIAS);

    float acc[4][4][4];
#pragma unroll
    for (int ms = 0; ms < 4; ms++)
#pragma unroll
        for (int nf = 0; nf < 4; nf++)
#pragma unroll
            for (int q = 0; q < 4; q++) acc[ms][nf][q] = 0.0f;

    // prefetch cursor (pf_T, pf_i) and current cursor (cur_T, cur_i)
    int cur_T = blockIdx.x, cur_i = 0;
    int pf_T  = blockIdx.x, pf_i  = 0;

    stage_chunk(sbase, tid, utap, pf_T, pf_i, 0);
    CP_COMMIT();
    if (++pf_i == nc) { pf_i = 0; pf_T += NCTA; }
    stage_chunk(sbase, tid, utap, pf_T, pf_i, 1);
    CP_COMMIT();
    if (++pf_i == nc) { pf_i = 0; pf_T += NCTA; }

    int s = 0;
    for (int ci = 0; ci < total; ci++) {
        if (ci + 1 < total) { CP_WAIT1(); } else { CP_WAIT0(); }
        __syncthreads();            // everyone finished compute(ci-1)
        if (ci + 2 < total) {       // prefetch into buffer (ci+2)%3
            int s2 = s + 2; if (s2 >= 3) s2 -= 3;
            stage_chunk(sbase, tid, utap, pf_T, pf_i, s2);
            CP_COMMIT();
            if (++pf_i == nc) { pf_i = 0; pf_T += NCTA; }
        }

        uint32_t stg = sbase + (uint32_t)s * STAGE_SZ;
#pragma unroll
        for (int ks = 0; ks < 4; ks++) {
            uint32_t af[4][4], bf[2][4];
            uint32_t akb = a_kb0 + (uint32_t)(ks * 32);
            uint32_t bkb = b_kb0 + (uint32_t)(ks * 32);
#pragma unroll
            for (int ms = 0; ms < 4; ms++)
                ldsm4(af[ms], stg + ST_A + a_rowoff + (uint32_t)(ms * 2048) + (akb ^ a_swz));
#pragma unroll
            for (int ns = 0; ns < 2; ns++)
                ldsm4(bf[ns], stg + ST_B + b_rowoff + (uint32_t)(ns * 2048) + (bkb ^ b_swz));
#pragma unroll
            for (int ms = 0; ms < 4; ms++)
#pragma unroll
                for (int nf = 0; nf < 4; nf++)
                    mma16816(acc[ms][nf], af[ms], &bf[nf >> 1][(nf & 1) * 2]);
        }
        if (++s >= 3) s = 0;

        // tile finished? epilogue + reset accumulators
        if (++cur_i == nc) {
            int mt = cur_T & 1;
            int b  = (cur_T >> 1) & 15;
            int h0 = (cur_T >> 5) << 1;
            int h = h0 + (wn >> 1);
            int wbase = (wn & 1) * 32;
#pragma unroll
            for (int ms = 0; ms < 4; ms++) {
#pragma unroll
                for (int half = 0; half < 2; half++) {
                    int rm = wm * 64 + ms * 16 + (lane >> 2) + half * 8;
                    int gout = mt * 4 + (rm >> 5);
                    int cout = rm & 31;
                    float bv = sb[cout];
                    float* ob = out + (((size_t)b * 32 + cout) * 8 + gout) * 4096 + h * 64;
#pragma unroll
                    for (int nf = 0; nf < 4; nf++) {
                        int w = wbase + nf * 8 + (lane & 3) * 2;
                        float2 v;
                        v.x = acc[ms][nf][half * 2 + 0] + bv;
                        v.y = acc[ms][nf][half * 2 + 1] + bv;
                        *(float2*)(ob + w) = v;
                    }
                }
            }
#pragma unroll
            for (int ms = 0; ms < 4; ms++)
#pragma unroll
                for (int nf = 0; nf < 4; nf++)
#pragma unroll
                    for (int q = 0; q < 4; q++) acc[ms][nf][q] = 0.0f;
            cur_i = 0;
            cur_T += NCTA;
        }
    }
}

// ---------------------------------------------------------------------------
extern "C" void kernel_launch(void* const* d_in, const int* in_sizes, int n_in,
                              void* d_out, int out_size) {
    const float* x    = (const float*)d_in[0];
    const float* ge   = (const float*)d_in[1];
    const float* W1   = (const float*)d_in[2];
    const float* b1   = (const float*)d_in[3];
    const float* W2   = (const float*)d_in[4];
    const float* b2   = (const float*)d_in[5];
    const float* W3   = (const float*)d_in[6];
    const float* b3   = (const float*)d_in[7];
    const float* bias = (const float*)d_in[8];
    float* out = (float*)d_out;

    cudaFuncSetAttribute(conv_kernel, cudaFuncAttributeMaxDynamicSharedMemorySize, SMEM_DYN);

    mask_kernel<<<1, 64>>>(ge);
    xt_kernel<<<dim3(64, 16, 2), 256>>>(x);
    siren_kernel<<<256, 256>>>(ge, W1, b1, W2, b2, W3, b3);
    conv_kernel<<<NCTA, 256, SMEM_DYN>>>(bias, out);
}

// round 17
// speedup vs baseline: 1.7927x; 1.0014x over previous
#include <cuda_runtime.h>
#include <cuda_fp16.h>
#include <math.h>
#include <stdint.h>

#define G_     8
#define KS_    7
#define NTAP_  49
#define HID_   32
#define OMEGA_ 10.0f

// ---------------------------------------------------------------------------
// Device globals (static — no allocation)
// ---------------------------------------------------------------------------
__device__ __align__(256) __half d_A[2 * NTAP_ * 4 * 128 * 64];    // 3.2MB
__device__ __align__(256) __half d_xT[16 * 4096 * 256];            // 16.8MB

// ---------------------------------------------------------------------------
// PTX helpers (baseline sm_80-class only: compiles for .target sm_103)
// ---------------------------------------------------------------------------
__device__ __forceinline__ uint32_t smem_u32(const void* p) {
    uint32_t a;
    asm("{ .reg .u64 t; cvta.to.shared.u64 t, %1; cvt.u32.u64 %0, t; }" : "=r"(a) : "l"(p));
    return a;
}
__device__ __forceinline__ void cp16(uint32_t dst, const void* src, uint32_t sz) {
    asm volatile("cp.async.cg.shared.global [%0], [%1], 16, %2;"
                 :: "r"(dst), "l"(src), "r"(sz) : "memory");
}
#define CP_COMMIT() asm volatile("cp.async.commit_group;" ::: "memory")
#define CP_WAIT1()  asm volatile("cp.async.wait_group 1;" ::: "memory")
#define CP_WAIT0()  asm volatile("cp.async.wait_group 0;" ::: "memory")

__device__ __forceinline__ void ldsm4(uint32_t* r, uint32_t a) {
    asm volatile("ldmatrix.sync.aligned.m8n8.x4.shared.b16 {%0,%1,%2,%3}, [%4];"
                 : "=r"(r[0]), "=r"(r[1]), "=r"(r[2]), "=r"(r[3]) : "r"(a));
}
__device__ __forceinline__ void mma16816(float* d, const uint32_t* a, const uint32_t* b) {
    asm volatile(
        "mma.sync.aligned.m16n8k16.row.col.f32.f16.f16.f32 "
        "{%0,%1,%2,%3}, {%4,%5,%6,%7}, {%8,%9}, {%0,%1,%2,%3};"
        : "+f"(d[0]), "+f"(d[1]), "+f"(d[2]), "+f"(d[3])
        : "r"(a[0]), "r"(a[1]), "r"(a[2]), "r"(a[3]), "r"(b[0]), "r"(b[1]));
}

// Replicate jnp.linspace(-1,1,7) fp32 exactly
__device__ __forceinline__ float grid_val(int i) {
    if (i == 6) return 1.0f;
    const float step = 2.0f / 6.0f;
    return __fadd_rn(__fmul_rn((float)i, step), -1.0f);
}

// Disk-mask test for tap t under rotation -theta. EXACT fp op sequence as the
// validated mask/siren path (no FMA contraction, libdevice sinf/cosf).
__device__ __forceinline__ int tap_in_disk(int t, float th) {
    float y = grid_val(t / KS_);
    float x = grid_val(t % KS_);
    float ct = cosf(-th), st = sinf(-th);
    float ny = __fadd_rn(__fmul_rn(ct, y), -__fmul_rn(st, x));
    float nx = __fadd_rn(__fmul_rn(st, y),  __fmul_rn(ct, x));
    float ss = __fadd_rn(__fmul_rn(ny, ny), __fmul_rn(nx, nx));
    return (sqrtf(ss) <= 1.0f) ? 1 : 0;
}

// ---------------------------------------------------------------------------
// Transpose + fp16 convert: x[b][c][pix] -> xT[b][pix][c]
// ---------------------------------------------------------------------------
__global__ void xt_kernel(const float* __restrict__ x) {
    __shared__ float s[64][129];
    int p0 = blockIdx.x * 64;
    int b  = blockIdx.y;
    int c0 = blockIdx.z * 128;
    int tid = threadIdx.x;
    int c_off = tid >> 6;
    int px = tid & 63;
    const float* xb = x + (size_t)b * 256 * 4096 + p0 + px;
#pragma unroll 4
    for (int cb = 0; cb < 32; cb++) {
        int cl = cb * 4 + c_off;
        s[px][cl] = xb[(size_t)(c0 + cl) * 4096];
    }
    __syncthreads();
#pragma unroll
    for (int r = 0; r < 4; r++) {
        int idx = tid + r * 256;       // 0..1023
        int p = idx >> 4;              // 0..63
        int u = idx & 15;              // 16 uint4 per 128-ch half
        __half hb[8];
#pragma unroll
        for (int e = 0; e < 8; e++)
            hb[e] = __float2half_rn(s[p][u * 8 + e]);
        size_t dst = ((size_t)b * 4096 + p0 + p) * 256 + c0 + u * 8;
        *(uint4*)(d_xT + dst) = *(uint4*)hb;
    }
}

// ---------------------------------------------------------------------------
// SIREN kernel-net -> masked fp16 A tiles [mt][tap][cc][m=128][k=64]
// grid 256: (gout, gin, oq). Mask computed inline from pts (same fp ops).
// ---------------------------------------------------------------------------
__global__ void siren_kernel(const float* __restrict__ ge,
                             const float* __restrict__ W1, const float* __restrict__ b1,
                             const float* __restrict__ W2, const float* __restrict__ b2,
                             const float* __restrict__ W3, const float* __restrict__ b3) {
    __shared__ float pts[NTAP_ * 3];
    __shared__ float h1[NTAP_ * HID_];
    __shared__ float h2[NTAP_ * HID_];
    __shared__ int   s_mask[NTAP_];

    int gout = blockIdx.x >> 5;
    int gin  = (blockIdx.x >> 2) & 7;
    int oq   = blockIdx.x & 3;
    int tid  = threadIdx.x;

    if (tid < NTAP_) {
        float tho = ge[gout];
        float thi = ge[gin];
        float ct = cosf(-tho);
        float st = sinf(-tho);
        const float twopi = 6.28318530717958647692f;
        const float pif   = 3.14159265358979323846f;
        float d = __fadd_rn(thi, -tho);
        float m = fmodf(d, twopi);
        if (m < 0.0f) m = __fadd_rn(m, twopi);
        float ag = __fadd_rn(__fdiv_rn(m, pif), -1.0f);
        float y = grid_val(tid / KS_);
        float x = grid_val(tid % KS_);
        float ny = __fadd_rn(__fmul_rn(ct, y), -__fmul_rn(st, x));
        float nx = __fadd_rn(__fmul_rn(st, y),  __fmul_rn(ct, x));
        pts[tid * 3 + 0] = ny;
        pts[tid * 3 + 1] = nx;
        pts[tid * 3 + 2] = ag;
        float ss = __fadd_rn(__fmul_rn(ny, ny), __fmul_rn(nx, nx));
        s_mask[tid] = (sqrtf(ss) <= 1.0f) ? 1 : 0;
    }
    __syncthreads();

    for (int i = tid; i < NTAP_ * HID_; i += 256) {
        int t = i >> 5, h = i & 31;
        float v = b1[h];
        v = fmaf(pts[t * 3 + 0], W1[0 * HID_ + h], v);
        v = fmaf(pts[t * 3 + 1], W1[1 * HID_ + h], v);
        v = fmaf(pts[t * 3 + 2], W1[2 * HID_ + h], v);
        h1[i] = sinf(OMEGA_ * v);
    }
    __syncthreads();

    for (int i = tid; i < NTAP_ * HID_; i += 256) {
        int t = i >> 5, h = i & 31;
        float v = b2[h];
#pragma unroll
        for (int k = 0; k < HID_; k++)
            v = fmaf(h1[t * HID_ + k], W2[k * HID_ + h], v);
        h2[i] = sinf(OMEGA_ * v);
    }
    __syncthreads();

    // quarter of the 49*1024 layer-3 outputs (contiguous range)
    for (int ii = tid; ii < NTAP_ * 256; ii += 256) {
        int i = oq * (NTAP_ * 256) + ii;
        int t = i >> 10, o = i & 1023;
        float v = b3[o];
#pragma unroll
        for (int k = 0; k < HID_; k++)
            v = fmaf(h2[t * HID_ + k], W3[k * 1024 + o], v);
        if (!s_mask[t]) v = 0.0f;
        int cout = o >> 5, cin = o & 31;
        int c = cin * G_ + gin;
        int mt = gout >> 2, m = ((gout & 3) << 5) + cout;
        size_t addr = ((size_t)((mt * NTAP_ + t) * 4 + (c >> 6))) * 8192 + m * 64 + (c & 63);
        d_A[addr] = __float2half_rn(v);
    }
}

// ---------------------------------------------------------------------------
// HMMA conv: PERSISTENT flat cross-tile chunk stream, 296 CTAs (2/SM),
// 256 threads / 8 warps, block tile M=128 x N=128px, warp 64x32, K-chunk=64,
// single-term fp16, 3-stage cp.async pipeline (1 sync/chunk). Union tap list
// computed per-CTA at startup (mask kernel fused away). LDSMs strictly AFTER
// the chunk barrier (cp.async completion is per-thread; the barrier is what
// makes other threads' copies visible).
// ---------------------------------------------------------------------------
#define ST_A     0
#define ST_B     16384
#define STAGE_SZ 32768
#define SM_BIAS  (3 * STAGE_SZ)
#define SM_UTAP  (SM_BIAS + 128)
#define SM_NU    (SM_UTAP + 4 * NTAP_)
#define SM_FLAG  (SM_NU + 16)
#define SMEM_DYN (SM_FLAG + 4 * NTAP_ + 16)
#define NCTA     296

// stage chunk i of tile T into buffer s
__device__ __forceinline__ void stage_chunk(uint32_t sbase, int tid,
                                            const int* utap, int T, int i, int s) {
    int mt = T & 1;
    int b  = (T >> 1) & 15;
    int h0 = (T >> 5) << 1;
    int tap = utap[i >> 2];
    int cc  = i & 3;
    uint32_t stg = sbase + (uint32_t)s * STAGE_SZ;

    // A: [128m x 64k] rows of 128B, 16B-XOR swizzle (4 uint4/thread)
    const char* ga = (const char*)(d_A + (size_t)((mt * NTAP_ + tap) * 4 + cc) * 8192);
#pragma unroll
    for (int r = 0; r < 4; r++) {
        int idx = tid + (r << 8);
        int m = idx >> 3, u = idx & 7;
        uint32_t d = (uint32_t)(m * 128 + ((u * 16) ^ ((m & 7) << 4)));
        cp16(stg + ST_A + d, ga + idx * 16, 16);
    }
    // B: 128 pixel rows x 64k (128B); 2 threads per pixel, 4 uint4 each
    int dy = tap / KS_ - 3, dx = tap % KS_ - 3;
    int pix  = tid >> 1;
    int half = tid & 1;
    int hh = h0 + (pix >> 6) + dy;
    int ww = (pix & 63) + dx;
    bool ok = (hh >= 0) && (hh < 64) && (ww >= 0) && (ww < 64);
    size_t gpix = ok ? ((size_t)b * 4096 + (size_t)hh * 64 + ww) : 0;
    const char* gb = (const char*)(d_xT + gpix * 256 + cc * 64);
    uint32_t sz = ok ? 16u : 0u;
    uint32_t rowbase = (uint32_t)(pix * 128);
    uint32_t sw = (uint32_t)((pix & 7) << 4);
#pragma unroll
    for (int u = 0; u < 4; u++) {
        int uu = half * 4 + u;
        uint32_t d = rowbase + ((uu * 16) ^ sw);
        cp16(stg + d + ST_B, gb + uu * 16, sz);
    }
}

__global__ void __launch_bounds__(256, 2)
conv_kernel(const float* __restrict__ ge, const float* __restrict__ bias,
            float* __restrict__ out) {
    extern __shared__ char sm[];
    uint32_t sbase = smem_u32(sm);
    int tid  = threadIdx.x;
    int lane = tid & 31;
    int wid  = tid >> 5;
    int wm   = wid & 1;     // M half (64 rows)
    int wn   = wid >> 1;    // N 32-px block (0..3)

    if (tid < 32) ((float*)(sm + SM_BIAS))[tid] = bias[tid];
    // union disk mask over all 8 gouts (exact fp ops of the validated path)
    if (tid >= 128 && tid < 128 + NTAP_) {
        int t = tid - 128;
        int u = 0;
        for (int g = 0; g < G_; g++)
            u |= tap_in_disk(t, ge[g]);
        ((int*)(sm + SM_FLAG))[t] = u;
    }
    __syncthreads();
    if (tid == 0) {
        int n = 0;
        const int* fl = (const int*)(sm + SM_FLAG);
        int* ut = (int*)(sm + SM_UTAP);
        for (int i = 0; i < NTAP_; i++)
            if (fl[i]) ut[n++] = i;
        *((int*)(sm + SM_NU)) = n;
    }
    __syncthreads();

    const int* utap = (const int*)(sm + SM_UTAP);
    int nu = *((const int*)(sm + SM_NU));
    int nc = nu << 2;

    // number of tiles for this CTA, total chunk count
    int ntile = 0;
    for (int T = blockIdx.x; T < 1024; T += NCTA) ntile++;
    if (ntile == 0) return;
    int total = ntile * nc;

    // B LDSM geometry (constant):
    int brow = wn * 32 + (lane & 7) + ((lane & 16) >> 1);   // + ns*16
    uint32_t b_rowoff = (uint32_t)(brow * 128);
    uint32_t b_kb0    = (uint32_t)((lane & 8) << 1);
    uint32_t b_swz    = (uint32_t)((brow & 7) << 4);
    // A LDSM geometry (constant):
    int arow = wm * 64 + (lane & 15);                       // + ms*16
    uint32_t a_rowoff = (uint32_t)(arow * 128);
    uint32_t a_kb0    = (uint32_t)((lane >> 4) << 4);
    uint32_t a_swz    = (uint32_t)((arow & 7) << 4);

    const float* sb = (const float*)(sm + SM_BIAS);

    float acc[4][4][4];
#pragma unroll
    for (int ms = 0; ms < 4; ms++)
#pragma unroll
        for (int nf = 0; nf < 4; nf++)
#pragma unroll
            for (int q = 0; q < 4; q++) acc[ms][nf][q] = 0.0f;

    // prefetch cursor (pf_T, pf_i) and current cursor (cur_T, cur_i)
    int cur_T = blockIdx.x, cur_i = 0;
    int pf_T  = blockIdx.x, pf_i  = 0;

    stage_chunk(sbase, tid, utap, pf_T, pf_i, 0);
    CP_COMMIT();
    if (++pf_i == nc) { pf_i = 0; pf_T += NCTA; }
    stage_chunk(sbase, tid, utap, pf_T, pf_i, 1);
    CP_COMMIT();
    if (++pf_i == nc) { pf_i = 0; pf_T += NCTA; }

    int s = 0;
    for (int ci = 0; ci < total; ci++) {
        if (ci + 1 < total) { CP_WAIT1(); } else { CP_WAIT0(); }
        __syncthreads();            // makes ALL threads' cp.async to buf s visible
        if (ci + 2 < total) {       // prefetch into buffer (ci+2)%3
            int s2 = s + 2; if (s2 >= 3) s2 -= 3;
            stage_chunk(sbase, tid, utap, pf_T, pf_i, s2);
            CP_COMMIT();
            if (++pf_i == nc) { pf_i = 0; pf_T += NCTA; }
        }

        uint32_t stg = sbase + (uint32_t)s * STAGE_SZ;
#pragma unroll
        for (int ks = 0; ks < 4; ks++) {
            uint32_t af[4][4], bf[2][4];
            uint32_t akb = a_kb0 + (uint32_t)(ks * 32);
            uint32_t bkb = b_kb0 + (uint32_t)(ks * 32);
#pragma unroll
            for (int ms = 0; ms < 4; ms++)
                ldsm4(af[ms], stg + ST_A + a_rowoff + (uint32_t)(ms * 2048) + (akb ^ a_swz));
#pragma unroll
            for (int ns = 0; ns < 2; ns++)
                ldsm4(bf[ns], stg + ST_B + b_rowoff + (uint32_t)(ns * 2048) + (bkb ^ b_swz));
#pragma unroll
            for (int ms = 0; ms < 4; ms++)
#pragma unroll
                for (int nf = 0; nf < 4; nf++)
                    mma16816(acc[ms][nf], af[ms], &bf[nf >> 1][(nf & 1) * 2]);
        }
        if (++s >= 3) s = 0;

        // tile finished? epilogue + reset accumulators
        if (++cur_i == nc) {
            int mt = cur_T & 1;
            int b  = (cur_T >> 1) & 15;
            int h0 = (cur_T >> 5) << 1;
            int h = h0 + (wn >> 1);
            int wbase = (wn & 1) * 32;
#pragma unroll
            for (int ms = 0; ms < 4; ms++) {
#pragma unroll
                for (int half = 0; half < 2; half++) {
                    int rm = wm * 64 + ms * 16 + (lane >> 2) + half * 8;
                    int gout = mt * 4 + (rm >> 5);
                    int cout = rm & 31;
                    float bv = sb[cout];
                    float* ob = out + (((size_t)b * 32 + cout) * 8 + gout) * 4096 + h * 64;
#pragma unroll
                    for (int nf = 0; nf < 4; nf++) {
                        int w = wbase + nf * 8 + (lane & 3) * 2;
                        float2 v;
                        v.x = acc[ms][nf][half * 2 + 0] + bv;
                        v.y = acc[ms][nf][half * 2 + 1] + bv;
                        *(float2*)(ob + w) = v;
                    }
                }
            }
#pragma unroll
            for (int ms = 0; ms < 4; ms++)
#pragma unroll
                for (int nf = 0; nf < 4; nf++)
#pragma unroll
                    for (int q = 0; q < 4; q++) acc[ms][nf][q] = 0.0f;
            cur_i = 0;
            cur_T += NCTA;
        }
    }
}

// ---------------------------------------------------------------------------
extern "C" void kernel_launch(void* const* d_in, const int* in_sizes, int n_in,
                              void* d_out, int out_size) {
    const float* x    = (const float*)d_in[0];
    const float* ge   = (const float*)d_in[1];
    const float* W1   = (const float*)d_in[2];
    const float* b1   = (const float*)d_in[3];
    const float* W2   = (const float*)d_in[4];
    const float* b2   = (const float*)d_in[5];
    const float* W3   = (const float*)d_in[6];
    const float* b3   = (const float*)d_in[7];
    const float* bias = (const float*)d_in[8];
    float* out = (float*)d_out;

    cudaFuncSetAttribute(conv_kernel, cudaFuncAttributeMaxDynamicSharedMemorySize, SMEM_DYN);

    xt_kernel<<<dim3(64, 16, 2), 256>>>(x);
    siren_kernel<<<256, 256>>>(ge, W1, b1, W2, b2, W3, b3);
    conv_kernel<<<NCTA, 256, SMEM_DYN>>>(ge, bias, out);
}